// round 6
// baseline (speedup 1.0000x reference)
#include <cuda_runtime.h>
#include <math.h>

#define NB 16
#define HW 3136
#define CC 256
#define OH 224
#define OW 224
#define RR 16
#define KS 33
#define NOUT (NB*OH*OW)

__device__ float g_mask56[NB * HW];
__device__ float g_tmp[NOUT];

typedef unsigned long long u64;

// ---------------------------------------------------------------------------
// Kernel 1: per-pixel Mahalanobis distance, symmetric triangle, 2-D register
// tiling to cut L1 data-path traffic (the measured bottleneck: L1=85%).
// Thread tile: 8 cols x 4 batches -> 32B M + 16B d per row for 64 lane-FMAs
// (1.5 B/FMA vs 4.25 before). Warp tile: 64 cols x 16 batches.
// Triangle {(i,c): i<=c} over 4 col-blocks of 64: tiles (C,R), R<4(C+1),
// 16 rows each; 40 tiles; warp w owns {w, w+8, w+16, w+24, w+32} = exactly
// 3 full + 2 diagonal tiles per warp. Diagonal rows use weight 1/2 at i==c,
// so quad = 2 * total. M loaded as ld.global.v2.u64 -> u64 halves are col
// pairs feeding FFMA2 directly (no packing). Per-tile fold reads col-pair
// diffs from transposed sdT (stride 264 -> bank-conflict-free).
// ---------------------------------------------------------------------------
__global__ __launch_bounds__(256) void maha_kernel(
    const float* __restrict__ x, const float* __restrict__ mean,
    const float* __restrict__ M) {
  const int p = blockIdx.x;
  const int t = threadIdx.x;
  const int wid = t >> 5, lane = t & 31;
  const int cg = lane & 7;        // col group (8 cols each)
  const int bg = lane >> 3;       // batch group (4 batches each)
  __shared__ float sd[CC][NB];    // diff, channel-major  [256][16]
  __shared__ float sdT[NB][264];  // diff, batch-major, padded
  __shared__ float red[8][NB];

  {
    const float mu = mean[p * CC + t];
    const float* xp = x + (size_t)p * CC + t;
#pragma unroll
    for (int b = 0; b < NB; b++) {
      const float v = xp[(size_t)b * ((size_t)HW * CC)] - mu;
      sd[t][b] = v;
      sdT[b][t] = v;
    }
  }
  __syncthreads();

  const float* Mp = M + ((size_t)p << 16);

  u64 accg[4];
#pragma unroll
  for (int b = 0; b < 4; b++) accg[b] = 0ull;

#pragma unroll 1
  for (int s = 0; s < 5; s++) {
    const int k = wid + s * 8;
    const int C = (k < 4) ? 0 : (k < 12) ? 1 : (k < 24) ? 2 : 3;
    const int base4 = (C == 0) ? 0 : (C == 1) ? 4 : (C == 2) ? 12 : 24;
    const int R = k - base4;
    const int r0 = R << 4;
    const int c0 = (C << 6) + (cg << 3);   // this thread's first col
    const bool isdiag = (R >= 4 * C);

    u64 acct[16];                          // [cp*4 + b]
#pragma unroll
    for (int j = 0; j < 16; j++) acct[j] = 0ull;

    const char* mrow = (const char*)(Mp + (size_t)r0 * CC + c0);

    if (!isdiag) {
#pragma unroll 2
      for (int i = 0; i < 16; i++) {
        const ulonglong2 m01 = *(const ulonglong2*)(mrow);
        const ulonglong2 m23 = *(const ulonglong2*)(mrow + 16);
        mrow += CC * 4;
        const float4 d4 = *(const float4*)&sd[r0 + i][bg << 2];
        u64 db[4];
        asm("mov.b64 %0, {%1, %1};" : "=l"(db[0]) : "f"(d4.x));
        asm("mov.b64 %0, {%1, %1};" : "=l"(db[1]) : "f"(d4.y));
        asm("mov.b64 %0, {%1, %1};" : "=l"(db[2]) : "f"(d4.z));
        asm("mov.b64 %0, {%1, %1};" : "=l"(db[3]) : "f"(d4.w));
#pragma unroll
        for (int b = 0; b < 4; b++) {
          asm("fma.rn.f32x2 %0, %1, %2, %0;" : "+l"(acct[0 + b]) : "l"(m01.x), "l"(db[b]));
          asm("fma.rn.f32x2 %0, %1, %2, %0;" : "+l"(acct[4 + b]) : "l"(m01.y), "l"(db[b]));
          asm("fma.rn.f32x2 %0, %1, %2, %0;" : "+l"(acct[8 + b]) : "l"(m23.x), "l"(db[b]));
          asm("fma.rn.f32x2 %0, %1, %2, %0;" : "+l"(acct[12 + b]) : "l"(m23.y), "l"(db[b]));
        }
      }
    } else {
#pragma unroll 2
      for (int i = 0; i < 16; i++) {
        const int ia = r0 + i;
        float4 ma = *(const float4*)(mrow);
        float4 mb = *(const float4*)(mrow + 16);
        mrow += CC * 4;
        // weight: 1 if i < c, 1/2 if i == c, 0 if i > c  (quad = 2 * sum)
        ma.x = (ia < c0 + 0) ? ma.x : (ia == c0 + 0) ? 0.5f * ma.x : 0.f;
        ma.y = (ia < c0 + 1) ? ma.y : (ia == c0 + 1) ? 0.5f * ma.y : 0.f;
        ma.z = (ia < c0 + 2) ? ma.z : (ia == c0 + 2) ? 0.5f * ma.z : 0.f;
        ma.w = (ia < c0 + 3) ? ma.w : (ia == c0 + 3) ? 0.5f * ma.w : 0.f;
        mb.x = (ia < c0 + 4) ? mb.x : (ia == c0 + 4) ? 0.5f * mb.x : 0.f;
        mb.y = (ia < c0 + 5) ? mb.y : (ia == c0 + 5) ? 0.5f * mb.y : 0.f;
        mb.z = (ia < c0 + 6) ? mb.z : (ia == c0 + 6) ? 0.5f * mb.z : 0.f;
        mb.w = (ia < c0 + 7) ? mb.w : (ia == c0 + 7) ? 0.5f * mb.w : 0.f;
        u64 mm[4];
        asm("mov.b64 %0, {%1, %2};" : "=l"(mm[0]) : "f"(ma.x), "f"(ma.y));
        asm("mov.b64 %0, {%1, %2};" : "=l"(mm[1]) : "f"(ma.z), "f"(ma.w));
        asm("mov.b64 %0, {%1, %2};" : "=l"(mm[2]) : "f"(mb.x), "f"(mb.y));
        asm("mov.b64 %0, {%1, %2};" : "=l"(mm[3]) : "f"(mb.z), "f"(mb.w));
        const float4 d4 = *(const float4*)&sd[ia][bg << 2];
        u64 db[4];
        asm("mov.b64 %0, {%1, %1};" : "=l"(db[0]) : "f"(d4.x));
        asm("mov.b64 %0, {%1, %1};" : "=l"(db[1]) : "f"(d4.y));
        asm("mov.b64 %0, {%1, %1};" : "=l"(db[2]) : "f"(d4.z));
        asm("mov.b64 %0, {%1, %1};" : "=l"(db[3]) : "f"(d4.w));
#pragma unroll
        for (int b = 0; b < 4; b++) {
          asm("fma.rn.f32x2 %0, %1, %2, %0;" : "+l"(acct[0 + b]) : "l"(mm[0]), "l"(db[b]));
          asm("fma.rn.f32x2 %0, %1, %2, %0;" : "+l"(acct[4 + b]) : "l"(mm[1]), "l"(db[b]));
          asm("fma.rn.f32x2 %0, %1, %2, %0;" : "+l"(acct[8 + b]) : "l"(mm[2]), "l"(db[b]));
          asm("fma.rn.f32x2 %0, %1, %2, %0;" : "+l"(acct[12 + b]) : "l"(mm[3]), "l"(db[b]));
        }
      }
    }

    // fold: accg[b] += {S_ce, S_co} * {d[b][ce], d[b][co]} per col pair
#pragma unroll
    for (int cp = 0; cp < 4; cp++) {
#pragma unroll
      for (int b = 0; b < 4; b++) {
        const u64 dp = *(const u64*)&sdT[(bg << 2) + b][c0 + 2 * cp];
        asm("fma.rn.f32x2 %0, %1, %2, %0;" : "+l"(accg[b]) : "l"(acct[cp * 4 + b]), "l"(dp));
      }
    }
  }

  // reduce: q[b] = lo+hi, sum over the 8 col-groups (lanes sharing bg)
  float q[4];
#pragma unroll
  for (int b = 0; b < 4; b++) {
    float lo, hi;
    asm("mov.b64 {%0, %1}, %2;" : "=f"(lo), "=f"(hi) : "l"(accg[b]));
    q[b] = lo + hi;
  }
#pragma unroll
  for (int off = 1; off < 8; off <<= 1) {
#pragma unroll
    for (int b = 0; b < 4; b++)
      q[b] += __shfl_xor_sync(0xffffffffu, q[b], off);
  }
  if (cg == 0) {
#pragma unroll
    for (int b = 0; b < 4; b++) red[wid][(bg << 2) + b] = q[b];
  }
  __syncthreads();
  if (t < NB) {
    float s = 0.f;
#pragma unroll
    for (int w = 0; w < 8; w++) s += red[w][t];
    g_mask56[t * HW + p] = sqrtf(fmaxf(2.0f * s, 0.f));
  }
}

__device__ __forceinline__ int reflect101(int i) {
  if (i < 0) i = -i;
  if (i > 223) i = 446 - i;
  return i;
}

__device__ __forceinline__ void load_weights(float* w, float* inv) {
  const int tid = threadIdx.x;
  if (tid < KS) {
    const float d = (float)(tid - RR);
    w[tid] = expf(-(d * d) / 32.0f);
  }
  __syncthreads();
  if (tid == 0) {
    float s = 0.f;
    for (int j = 0; j < KS; j++) s += w[j];
    *inv = 1.0f / s;
  }
}

// ---------------------------------------------------------------------------
// Kernel 2: FUSED bilinear resize (56->224) + vertical blur; zeroes scores.
// ---------------------------------------------------------------------------
__global__ __launch_bounds__(256) void blur_v_kernel(float* __restrict__ score) {
  __shared__ float s[OH + 32][17];
  __shared__ float w[KS];
  __shared__ float inv;
  load_weights(w, &inv);
  const int tid = threadIdx.x;
  if (blockIdx.x == 0 && tid < NB) score[tid] = 0.0f;
  const int b = blockIdx.x / 14;
  const int xt = (blockIdx.x % 14) * 16;
  const float* mp = g_mask56 + b * HW;
#pragma unroll
  for (int li = tid; li < (OH + 32) * 16; li += 256) {
    const int r = li >> 4, c = li & 15;
    const int gy = reflect101(r - RR);
    const int gx = xt + c;
    const float fy = (gy + 0.5f) * 0.25f - 0.5f;
    const float fx = (gx + 0.5f) * 0.25f - 0.5f;
    const int y0 = (int)floorf(fy);
    const int x0 = (int)floorf(fx);
    const float wy = fy - (float)y0;
    const float wx = fx - (float)x0;
    const int y0c = min(max(y0, 0), 55), y1c = min(max(y0 + 1, 0), 55);
    const int x0c = min(max(x0, 0), 55), x1c = min(max(x0 + 1, 0), 55);
    const float v00 = mp[y0c * 56 + x0c];
    const float v01 = mp[y0c * 56 + x1c];
    const float v10 = mp[y1c * 56 + x0c];
    const float v11 = mp[y1c * 56 + x1c];
    s[r][c] = (1.f - wy) * ((1.f - wx) * v00 + wx * v01) +
              wy * ((1.f - wx) * v10 + wx * v11);
  }
  __syncthreads();
  float* dst = g_tmp + b * OH * OW + xt;
  const int c = tid & 15;
  for (int y = tid >> 4; y < OH; y += 16) {
    float sum = 0.f;
#pragma unroll
    for (int j = 0; j < KS; j++) sum += w[j] * s[y + j][c];
    dst[y * OW + c] = sum * inv;
  }
}

// ---------------------------------------------------------------------------
// Kernel 3: horizontal blur + per-batch max.
// ---------------------------------------------------------------------------
__global__ __launch_bounds__(256) void blur_h_kernel(float* __restrict__ out_mask,
                                                     float* __restrict__ score) {
  __shared__ float s[8][256];
  __shared__ float w[KS];
  __shared__ float inv;
  __shared__ float smx[8];
  load_weights(w, &inv);
  const int tid = threadIdx.x;
  const int b = blockIdx.x / 28;
  const int yt = (blockIdx.x % 28) * 8;
  const float* src = g_tmp + (b * OH + yt) * OW;
#pragma unroll
  for (int li = tid; li < 8 * 256; li += 256) {
    const int r = li >> 8, c = li & 255;
    const int gx = reflect101(c - RR);
    s[r][c] = src[r * OW + gx];
  }
  __syncthreads();
  float* dst = out_mask + (b * OH + yt) * OW;
  const int lane = tid & 31;
  const int r = tid >> 5;
  float mx = 0.f;
#pragma unroll
  for (int x0 = 0; x0 < OW; x0 += 32) {
    const int x = x0 + lane;
    float sum = 0.f;
#pragma unroll
    for (int j = 0; j < KS; j++) sum += w[j] * s[r][x + j];
    sum *= inv;
    dst[r * OW + x] = sum;
    mx = fmaxf(mx, sum);
  }
#pragma unroll
  for (int off = 16; off > 0; off >>= 1)
    mx = fmaxf(mx, __shfl_down_sync(0xffffffffu, mx, off));
  if (lane == 0) smx[r] = mx;
  __syncthreads();
  if (tid == 0) {
    float m2 = smx[0];
#pragma unroll
    for (int k = 1; k < 8; k++) m2 = fmaxf(m2, smx[k]);
    atomicMax((int*)&score[b], __float_as_int(m2));
  }
}

extern "C" void kernel_launch(void* const* d_in, const int* in_sizes, int n_in,
                              void* d_out, int out_size) {
  const float* inputs = (const float*)d_in[0];    // [16,56,56,256]
  const float* mean = (const float*)d_in[1];      // [3136,256]
  const float* cvar_inv = (const float*)d_in[2];  // [3136,256,256]
  float* out = (float*)d_out;
  float* score = out;          // [16,1]
  float* mask = out + NB;      // [16,224,224,1]

  maha_kernel<<<HW, 256>>>(inputs, mean, cvar_inv);
  blur_v_kernel<<<16 * 14, 256>>>(score);
  blur_h_kernel<<<16 * 28, 256>>>(mask, score);
}

// round 7
// speedup vs baseline: 1.4549x; 1.4549x over previous
#include <cuda_runtime.h>
#include <math.h>

#define NB 16
#define HW 3136
#define CC 256
#define OH 224
#define OW 224
#define RR 16
#define KS 33
#define NOUT (NB*OH*OW)

__device__ float g_mask56[NB * HW];
__device__ float g_tmp[NOUT];

// ---------------------------------------------------------------------------
// Kernel 1: per-pixel Mahalanobis via tensor cores (tf32 split for fp32-class
// accuracy). quad[b] = sum_c V[b,c] * d[b,c],  V = D * M  (16x256x256 GEMM).
// Block = pixel (3136 x 256). Warp w owns N-cols [32w, 32w+32) as 4 n-tiles
// of m16n8k8. K loop: 8 rows/step. B fragments are loaded straight from GMEM
// in fragment order (lane t -> M[k0 + t%4 (+4)][n0 + t/4]): each LDG.32
// touches 4 full 32B sectors, M streamed once, coalesced. A fragments come
// from the diff in SMEM. Split tf32: x = hi + lo, D*M ~ hi*hi + hi*lo + lo*hi.
// ---------------------------------------------------------------------------
__global__ __launch_bounds__(256, 3) void maha_kernel(
    const float* __restrict__ x, const float* __restrict__ mean,
    const float* __restrict__ M) {
  const int p = blockIdx.x;
  const int t = threadIdx.x;
  const int wid = t >> 5, lane = t & 31;
  const int tq = lane & 3;    // k-offset within fragment
  const int tr = lane >> 2;   // row/col group index
  __shared__ float sd[CC][NB];   // diff: sd[channel][batch]  (16 KB)
  __shared__ float red[8][NB];

  {
    const float mu = mean[p * CC + t];
    const float* xp = x + (size_t)p * CC + t;
#pragma unroll
    for (int b = 0; b < NB; b++)
      sd[t][b] = xp[(size_t)b * ((size_t)HW * CC)] - mu;
  }
  __syncthreads();

  const float* Mp = M + ((size_t)p << 16);
  const int n0 = wid << 5;

  float c0[4], c1[4], c2[4], c3[4];
#pragma unroll
  for (int nt = 0; nt < 4; nt++) { c0[nt] = c1[nt] = c2[nt] = c3[nt] = 0.f; }

#pragma unroll 2
  for (int k0 = 0; k0 < CC; k0 += 8) {
    // ---- A fragment (16x8 of D): rows=batch, cols=k ----
    const float a0f = sd[k0 + tq][tr];
    const float a1f = sd[k0 + tq][tr + 8];
    const float a2f = sd[k0 + tq + 4][tr];
    const float a3f = sd[k0 + tq + 4][tr + 8];
    unsigned ah0, ah1, ah2, ah3;
    asm("cvt.rna.tf32.f32 %0, %1;" : "=r"(ah0) : "f"(a0f));
    asm("cvt.rna.tf32.f32 %0, %1;" : "=r"(ah1) : "f"(a1f));
    asm("cvt.rna.tf32.f32 %0, %1;" : "=r"(ah2) : "f"(a2f));
    asm("cvt.rna.tf32.f32 %0, %1;" : "=r"(ah3) : "f"(a3f));
    const unsigned al0 = __float_as_uint(a0f - __uint_as_float(ah0));
    const unsigned al1 = __float_as_uint(a1f - __uint_as_float(ah1));
    const unsigned al2 = __float_as_uint(a2f - __uint_as_float(ah2));
    const unsigned al3 = __float_as_uint(a3f - __uint_as_float(ah3));

    const float* Mk = Mp + (size_t)(k0 + tq) * CC + n0 + tr;

#pragma unroll
    for (int nt = 0; nt < 4; nt++) {
      // ---- B fragment (8x8 of M): b0 = M[k0+tq][col], b1 = M[k0+tq+4][col]
      const float b0f = Mk[nt * 8];
      const float b1f = Mk[nt * 8 + 4 * CC];
      unsigned bh0, bh1;
      asm("cvt.rna.tf32.f32 %0, %1;" : "=r"(bh0) : "f"(b0f));
      asm("cvt.rna.tf32.f32 %0, %1;" : "=r"(bh1) : "f"(b1f));
      const unsigned bl0 = __float_as_uint(b0f - __uint_as_float(bh0));
      const unsigned bl1 = __float_as_uint(b1f - __uint_as_float(bh1));

      asm("mma.sync.aligned.m16n8k8.row.col.f32.tf32.tf32.f32 "
          "{%0,%1,%2,%3}, {%4,%5,%6,%7}, {%8,%9}, {%0,%1,%2,%3};"
          : "+f"(c0[nt]), "+f"(c1[nt]), "+f"(c2[nt]), "+f"(c3[nt])
          : "r"(ah0), "r"(ah1), "r"(ah2), "r"(ah3), "r"(bh0), "r"(bh1));
      asm("mma.sync.aligned.m16n8k8.row.col.f32.tf32.tf32.f32 "
          "{%0,%1,%2,%3}, {%4,%5,%6,%7}, {%8,%9}, {%0,%1,%2,%3};"
          : "+f"(c0[nt]), "+f"(c1[nt]), "+f"(c2[nt]), "+f"(c3[nt])
          : "r"(ah0), "r"(ah1), "r"(ah2), "r"(ah3), "r"(bl0), "r"(bl1));
      asm("mma.sync.aligned.m16n8k8.row.col.f32.tf32.tf32.f32 "
          "{%0,%1,%2,%3}, {%4,%5,%6,%7}, {%8,%9}, {%0,%1,%2,%3};"
          : "+f"(c0[nt]), "+f"(c1[nt]), "+f"(c2[nt]), "+f"(c3[nt])
          : "r"(al0), "r"(al1), "r"(al2), "r"(al3), "r"(bh0), "r"(bh1));
    }
  }

  // ---- epilogue: q[b] += V[b,n] * d[b,n] over this warp's 32 cols ----
  // C frag: c0:(tr, 2tq) c1:(tr, 2tq+1) c2:(tr+8, 2tq) c3:(tr+8, 2tq+1)
  float q0 = 0.f, q1 = 0.f;
#pragma unroll
  for (int nt = 0; nt < 4; nt++) {
    const int n = n0 + nt * 8 + tq * 2;
    q0 += c0[nt] * sd[n][tr]     + c1[nt] * sd[n + 1][tr];
    q1 += c2[nt] * sd[n][tr + 8] + c3[nt] * sd[n + 1][tr + 8];
  }
  q0 += __shfl_xor_sync(0xffffffffu, q0, 1);
  q0 += __shfl_xor_sync(0xffffffffu, q0, 2);
  q1 += __shfl_xor_sync(0xffffffffu, q1, 1);
  q1 += __shfl_xor_sync(0xffffffffu, q1, 2);
  if (tq == 0) {
    red[wid][tr] = q0;
    red[wid][tr + 8] = q1;
  }
  __syncthreads();
  if (t < NB) {
    float s = 0.f;
#pragma unroll
    for (int w = 0; w < 8; w++) s += red[w][t];
    g_mask56[t * HW + p] = sqrtf(fmaxf(s, 0.f));
  }
}

__device__ __forceinline__ int reflect101(int i) {
  if (i < 0) i = -i;
  if (i > 223) i = 446 - i;
  return i;
}

__device__ __forceinline__ void load_weights(float* w, float* inv) {
  const int tid = threadIdx.x;
  if (tid < KS) {
    const float d = (float)(tid - RR);
    w[tid] = expf(-(d * d) / 32.0f);
  }
  __syncthreads();
  if (tid == 0) {
    float s = 0.f;
    for (int j = 0; j < KS; j++) s += w[j];
    *inv = 1.0f / s;
  }
}

// ---------------------------------------------------------------------------
// Kernel 2: FUSED bilinear resize (56->224) + vertical blur; zeroes scores.
// ---------------------------------------------------------------------------
__global__ __launch_bounds__(256) void blur_v_kernel(float* __restrict__ score) {
  __shared__ float s[OH + 32][17];
  __shared__ float w[KS];
  __shared__ float inv;
  load_weights(w, &inv);
  const int tid = threadIdx.x;
  if (blockIdx.x == 0 && tid < NB) score[tid] = 0.0f;
  const int b = blockIdx.x / 14;
  const int xt = (blockIdx.x % 14) * 16;
  const float* mp = g_mask56 + b * HW;
#pragma unroll
  for (int li = tid; li < (OH + 32) * 16; li += 256) {
    const int r = li >> 4, c = li & 15;
    const int gy = reflect101(r - RR);
    const int gx = xt + c;
    const float fy = (gy + 0.5f) * 0.25f - 0.5f;
    const float fx = (gx + 0.5f) * 0.25f - 0.5f;
    const int y0 = (int)floorf(fy);
    const int x0 = (int)floorf(fx);
    const float wy = fy - (float)y0;
    const float wx = fx - (float)x0;
    const int y0c = min(max(y0, 0), 55), y1c = min(max(y0 + 1, 0), 55);
    const int x0c = min(max(x0, 0), 55), x1c = min(max(x0 + 1, 0), 55);
    const float v00 = mp[y0c * 56 + x0c];
    const float v01 = mp[y0c * 56 + x1c];
    const float v10 = mp[y1c * 56 + x0c];
    const float v11 = mp[y1c * 56 + x1c];
    s[r][c] = (1.f - wy) * ((1.f - wx) * v00 + wx * v01) +
              wy * ((1.f - wx) * v10 + wx * v11);
  }
  __syncthreads();
  float* dst = g_tmp + b * OH * OW + xt;
  const int c = tid & 15;
  for (int y = tid >> 4; y < OH; y += 16) {
    float sum = 0.f;
#pragma unroll
    for (int j = 0; j < KS; j++) sum += w[j] * s[y + j][c];
    dst[y * OW + c] = sum * inv;
  }
}

// ---------------------------------------------------------------------------
// Kernel 3: horizontal blur + per-batch max.
// ---------------------------------------------------------------------------
__global__ __launch_bounds__(256) void blur_h_kernel(float* __restrict__ out_mask,
                                                     float* __restrict__ score) {
  __shared__ float s[8][256];
  __shared__ float w[KS];
  __shared__ float inv;
  __shared__ float smx[8];
  load_weights(w, &inv);
  const int tid = threadIdx.x;
  const int b = blockIdx.x / 28;
  const int yt = (blockIdx.x % 28) * 8;
  const float* src = g_tmp + (b * OH + yt) * OW;
#pragma unroll
  for (int li = tid; li < 8 * 256; li += 256) {
    const int r = li >> 8, c = li & 255;
    const int gx = reflect101(c - RR);
    s[r][c] = src[r * OW + gx];
  }
  __syncthreads();
  float* dst = out_mask + (b * OH + yt) * OW;
  const int lane = tid & 31;
  const int r = tid >> 5;
  float mx = 0.f;
#pragma unroll
  for (int x0 = 0; x0 < OW; x0 += 32) {
    const int x = x0 + lane;
    float sum = 0.f;
#pragma unroll
    for (int j = 0; j < KS; j++) sum += w[j] * s[r][x + j];
    sum *= inv;
    dst[r * OW + x] = sum;
    mx = fmaxf(mx, sum);
  }
#pragma unroll
  for (int off = 16; off > 0; off >>= 1)
    mx = fmaxf(mx, __shfl_down_sync(0xffffffffu, mx, off));
  if (lane == 0) smx[r] = mx;
  __syncthreads();
  if (tid == 0) {
    float m2 = smx[0];
#pragma unroll
    for (int k = 1; k < 8; k++) m2 = fmaxf(m2, smx[k]);
    atomicMax((int*)&score[b], __float_as_int(m2));
  }
}

extern "C" void kernel_launch(void* const* d_in, const int* in_sizes, int n_in,
                              void* d_out, int out_size) {
  const float* inputs = (const float*)d_in[0];    // [16,56,56,256]
  const float* mean = (const float*)d_in[1];      // [3136,256]
  const float* cvar_inv = (const float*)d_in[2];  // [3136,256,256]
  float* out = (float*)d_out;
  float* score = out;          // [16,1]
  float* mask = out + NB;      // [16,224,224,1]

  maha_kernel<<<HW, 256>>>(inputs, mean, cvar_inv);
  blur_v_kernel<<<16 * 14, 256>>>(score);
  blur_h_kernel<<<16 * 28, 256>>>(mask, score);
}